// round 7
// baseline (speedup 1.0000x reference)
#include <cuda_runtime.h>

#define NROWS  512
#define DDIM   512
#define KSPLIT 14
#define NTILES 10          // upper-triangle 4x4 of 128-wide tiles
#define GEMM_GRID (NTILES * KSPLIT)   // 140 blocks ~ one wave

// Scratch (allocation-free rule: __device__ globals)
__device__ float g_embT[DDIM * NROWS];            // embT[k][m] = embs[m][k]
__device__ float g_part[KSPLIT * NROWS * NROWS];  // k-split partial dot products
__device__ float g_diag[KSPLIT][NROWS];           // k-split partial diag (norms^2)
__device__ int   g_idx32;                         // 1 if indices are int32

// ---------------------------------------------------------------------------
// Kernel 1: transpose embs -> g_embT. 256 blocks (16x16 tiles) x 256 threads.
// Block 0 zeroes the output scalar and probes the indices dtype.
// ---------------------------------------------------------------------------
__global__ void transpose_kernel(const float* __restrict__ embs,
                                 const int* __restrict__ idx32view,
                                 float* __restrict__ out) {
    __shared__ float tile[32][33];
    const int bx = blockIdx.x & 15;
    const int by = blockIdx.x >> 4;
    const int t  = threadIdx.x;
    const int r  = t >> 3;
    const int c4 = (t & 7) * 4;

    float4 v = *(const float4*)&embs[(by * 32 + r) * DDIM + bx * 32 + c4];
    tile[r][c4 + 0] = v.x; tile[r][c4 + 1] = v.y;
    tile[r][c4 + 2] = v.z; tile[r][c4 + 3] = v.w;
    __syncthreads();
    float4 o = make_float4(tile[c4 + 0][r], tile[c4 + 1][r],
                           tile[c4 + 2][r], tile[c4 + 3][r]);
    *(float4*)&g_embT[(bx * 32 + r) * NROWS + by * 32 + c4] = o;

    if (blockIdx.x == 0) {
        // Dtype probe: odd int32 positions within the first 2048 bytes.
        // int64 layout -> all zero (high words of values in [0,64)).
        // int32 layout -> real class IDs, essentially never all zero.
        __shared__ int fl;
        if (t == 0) { fl = 0; *out = 0.0f; }
        __syncthreads();
        if (idx32view[2 * t + 1] != 0) atomicOr(&fl, 1);
        __syncthreads();
        if (t == 0) g_idx32 = fl;
    }
}

// ---------------------------------------------------------------------------
// Kernel 2: dot GEMM from L1/L2, no smem. 140 blocks x 256 threads.
// 128x128 tiles (upper triangle, 10 tiles) x 14-way k-split.
// 8x8 register micro-tile: per k, 4x LDG.128 (64B) + 64 FFMA -> FFMA-bound.
// Writes plain partial sums; diagonal tiles emit diag partials for norms.
// ---------------------------------------------------------------------------
__global__ void __launch_bounds__(256, 1)
gemm_kernel() {
    const int tile = blockIdx.x / KSPLIT;   // 0..9
    const int s    = blockIdx.x % KSPLIT;   // k-split slice

    // tile -> (bm, bn) with bn >= bm over a 4x4 grid
    int rem = tile, bm = 0;
    while (rem >= 4 - bm) { rem -= 4 - bm; bm++; }
    const int bn = bm + rem;

    // k-slice: 512 = 8*37 + 6*36
    const int k0   = (s < 8) ? 37 * s : 296 + 36 * (s - 8);
    const int klen = (s < 8) ? 37 : 36;

    const int tx = threadIdx.x & 15;
    const int ty = threadIdx.x >> 4;
    const int aoff = bm * 128 + 8 * ty;
    const int boff = bn * 128 + 8 * tx;

    float acc[8][8];
#pragma unroll
    for (int i = 0; i < 8; i++)
#pragma unroll
        for (int j = 0; j < 8; j++) acc[i][j] = 0.f;

#pragma unroll 2
    for (int k = k0; k < k0 + klen; k++) {
        const float* __restrict__ rowk = g_embT + k * NROWS;
        float4 a0 = *(const float4*)(rowk + aoff);
        float4 a1 = *(const float4*)(rowk + aoff + 4);
        float4 b0 = *(const float4*)(rowk + boff);
        float4 b1 = *(const float4*)(rowk + boff + 4);
        float a[8] = {a0.x, a0.y, a0.z, a0.w, a1.x, a1.y, a1.z, a1.w};
        float b[8] = {b0.x, b0.y, b0.z, b0.w, b1.x, b1.y, b1.z, b1.w};
#pragma unroll
        for (int i = 0; i < 8; i++)
#pragma unroll
            for (int j = 0; j < 8; j++) acc[i][j] += a[i] * b[j];
    }

    float* __restrict__ outp = g_part + s * (NROWS * NROWS);
    const int row0 = bm * 128 + 8 * ty;
    const int col0 = bn * 128 + 8 * tx;
#pragma unroll
    for (int i = 0; i < 8; i++) {
        *(float4*)&outp[(row0 + i) * NROWS + col0]     =
            make_float4(acc[i][0], acc[i][1], acc[i][2], acc[i][3]);
        *(float4*)&outp[(row0 + i) * NROWS + col0 + 4] =
            make_float4(acc[i][4], acc[i][5], acc[i][6], acc[i][7]);
    }

    if (bm == bn && tx == ty) {
#pragma unroll
        for (int d = 0; d < 8; d++) g_diag[s][row0 + d] = acc[d][d];
    }
}

// ---------------------------------------------------------------------------
// Kernel 3: triplet sum, warp-per-anchor. 64 blocks x 256 threads.
// Balanced mapping: anchor = w*64 + blockIdx.x. Phase A: batched LDGs sum
// the 14 k-split partials per slot (deep MLP, no collectives in between).
// Phase B: uniform ballot compaction of positives. Hot loop: np x 16
// unrolled register fmax. One atomicAdd per block.
// ---------------------------------------------------------------------------
__global__ void triplet_kernel(const void* __restrict__ idxraw,
                               float* __restrict__ out) {
    const int tid  = threadIdx.x;
    const int w    = tid >> 5;
    const int lane = tid & 31;

    __shared__ float s_inv[NROWS];
    __shared__ int   s_cls[NROWS];
    __shared__ float s_pos[8][32];
    __shared__ float s_wsum[8];

    const int is32 = g_idx32;
    const int* __restrict__ i32 = (const int*)idxraw;
    const long long* __restrict__ i64 = (const long long*)idxraw;

#pragma unroll
    for (int e = 0; e < 2; e++) {
        int r = tid + e * 256;
        float d = 0.f;
#pragma unroll
        for (int p = 0; p < KSPLIT; p++) d += g_diag[p][r];   // coalesced
        s_inv[r] = 1.0f / fmaxf(sqrtf(d), 1e-8f);
        s_cls[r] = is32 ? i32[r] : (int)i64[r];
    }
    __syncthreads();

    const int i = w * 64 + blockIdx.x;        // balanced anchor mapping
    const int   ci   = s_cls[i];
    const float invi = s_inv[i];
    const int   rowbase = i * NROWS;

    // Phase A: batched partial-sum loads; no warp collectives here.
    float c[16];
#pragma unroll
    for (int slot = 0; slot < 16; slot++) {
        int j = i + 1 + lane + slot * 32;
        float sum = 0.f;
        if (j < NROWS) {
#pragma unroll
            for (int p = 0; p < KSPLIT; p++)
                sum += g_part[p * (NROWS * NROWS) + rowbase + j];
            sum *= invi * s_inv[j];
        }
        c[slot] = sum;
    }

    // Phase B: uniform ballot compaction (all lanes hit every ballot).
    int np = 0;
#pragma unroll
    for (int slot = 0; slot < 16; slot++) {
        int j = i + 1 + lane + slot * 32;
        bool valid = (j < NROWS);
        bool match = valid && (s_cls[j] == ci);
        unsigned mask = __ballot_sync(0xffffffffu, match);
        if (match) {
            int off = np + __popc(mask & ((1u << lane) - 1u));
            if (off < 32) s_pos[w][off] = c[slot];
        }
        np += __popc(mask);
        c[slot] = (valid && !match) ? (c[slot] + 1.0f) : -1e30f;  // sentinel
    }
    if (np > 32) np = 32;   // capacity guard (expected np ~ 4)
    __syncwarp();

    // Hot loop: np broadcast-LDS reads, 16 unrolled register fmax each.
    float s0 = 0.f, s1 = 0.f;
    for (int p = 0; p < np; p++) {
        float bp = s_pos[w][p];
#pragma unroll
        for (int slot = 0; slot < 16; slot += 2) {
            s0 += fmaxf(c[slot]     - bp, 0.0f);
            s1 += fmaxf(c[slot + 1] - bp, 0.0f);
        }
    }
    float s = s0 + s1;

#pragma unroll
    for (int o = 16; o; o >>= 1) s += __shfl_xor_sync(0xffffffffu, s, o);
    if (lane == 0) s_wsum[w] = s;
    __syncthreads();

    if (tid < 8) {
        float v = s_wsum[tid];
#pragma unroll
        for (int o = 4; o; o >>= 1) v += __shfl_xor_sync(0xffu, v, o);
        if (tid == 0) atomicAdd(out, v);   // one atomic per block (64 total)
    }
}

extern "C" void kernel_launch(void* const* d_in, const int* in_sizes, int n_in,
                              void* d_out, int out_size) {
    const float* embs = (const float*)d_in[0];
    const void*  indices = d_in[1];
    float* out = (float*)d_out;

    transpose_kernel<<<256, 256>>>(embs, (const int*)indices, out);
    gemm_kernel<<<GEMM_GRID, 256>>>();
    triplet_kernel<<<64, 256>>>(indices, out);
}

// round 8
// speedup vs baseline: 2.0961x; 2.0961x over previous
#include <cuda_runtime.h>

#define NROWS  512
#define DDIM   512
#define TILE   64
#define NT     8            // 512/64 tile-rows
#define NTILES 36           // upper triangle of 8x8
#define KSPLIT 4
#define KLEN   128          // 512/KSPLIT
#define GEMM_GRID (NTILES * KSPLIT)   // 144 blocks ~ one wave

// Scratch (allocation-free rule: __device__ globals)
__device__ float g_part[KSPLIT * NROWS * NROWS];  // k-split partial dots (upper tiles)
__device__ float g_diag[KSPLIT][NROWS];           // k-split partial diagonal
__device__ int   g_idx32;                         // 1 if indices are int32

// ---------------------------------------------------------------------------
// Kernel 1: dot GEMM. 144 blocks x 256 threads.
// 64x64 upper-triangle tiles (36) x 4-way k-split. 4x4 register micro-tile:
// per k, 2x LDS.128 + 16 FFMA (2 B/FMA) -> FFMA-bound, not crossbar-bound.
// Staging: 4x4 register transpose + XOR swizzle (quad = rb ^ kb) so both the
// float4 stores (4-cyc floor) and inner-loop reads are bank-conflict-free.
// Block 0 zeroes the output scalar and probes the indices dtype.
// ---------------------------------------------------------------------------
__global__ void __launch_bounds__(256, 1)
gemm_kernel(const float* __restrict__ embs,
            const int* __restrict__ idx32view,
            float* __restrict__ out) {
    const int tid = threadIdx.x;

    if (blockIdx.x == 0) {
        // Dtype probe: odd int32 positions within the first 2048 bytes.
        // int64 layout -> all zero (high words of values in [0,64)).
        // int32 layout -> real class IDs, essentially never all zero.
        __shared__ int fl;
        if (tid == 0) { fl = 0; *out = 0.0f; }
        __syncthreads();
        if (idx32view[2 * tid + 1] != 0) atomicOr(&fl, 1);
        __syncthreads();
        if (tid == 0) g_idx32 = fl;
    }

    const int tile = blockIdx.x >> 2;   // 0..35
    const int s    = blockIdx.x & 3;    // k-slice
    int rem = tile, bm = 0;
    while (rem >= NT - bm) { rem -= NT - bm; bm++; }
    const int bn = bm + rem;
    const int k0 = s * KLEN;

    // Staging roles: 128 threads per tile (A: tid<128, B: tid>=128).
    // kb = k-quad 0..7 (coalesced gmem dim), rb = row-quad 0..15.
    const int tsel = tid >> 7;
    const int tid7 = tid & 127;
    const int kb   = tid7 & 7;
    const int rb   = tid7 >> 3;
    const int baserow = (tsel ? bn : bm) * TILE + 4 * rb;
    const float* __restrict__ gsrc = embs + baserow * DDIM + k0 + 4 * kb;

    __shared__ float4 Ash4[32 * 16];    // [k][quad] swizzled, 8 KB
    __shared__ float4 Bsh4[32 * 16];
    float4* const dst = tsel ? Bsh4 : Ash4;

    const int tx = tid & 15;
    const int ty = tid >> 4;

    float acc[4][4];
#pragma unroll
    for (int i = 0; i < 4; i++)
#pragma unroll
        for (int j = 0; j < 4; j++) acc[i][j] = 0.f;

    for (int kk = 0; kk < KLEN; kk += 32) {
        // Load 4 rows x float4 (fully coalesced: 8 consecutive threads = 128B)
        float4 v0 = *(const float4*)(gsrc + kk);
        float4 v1 = *(const float4*)(gsrc + DDIM + kk);
        float4 v2 = *(const float4*)(gsrc + 2 * DDIM + kk);
        float4 v3 = *(const float4*)(gsrc + 3 * DDIM + kk);
        __syncthreads();                 // previous chunk fully consumed
        // Register transpose -> swizzled float4 stores (quad = rb ^ kb)
        const int q = rb ^ kb;
        dst[(4 * kb + 0) * 16 + q] = make_float4(v0.x, v1.x, v2.x, v3.x);
        dst[(4 * kb + 1) * 16 + q] = make_float4(v0.y, v1.y, v2.y, v3.y);
        dst[(4 * kb + 2) * 16 + q] = make_float4(v0.z, v1.z, v2.z, v3.z);
        dst[(4 * kb + 3) * 16 + q] = make_float4(v0.w, v1.w, v2.w, v3.w);
        __syncthreads();

#pragma unroll
        for (int k = 0; k < 32; k++) {
            const int sw = (k >> 2) & 7;
            float4 a = Ash4[k * 16 + (ty ^ sw)];
            float4 b = Bsh4[k * 16 + (tx ^ sw)];
            acc[0][0] += a.x * b.x; acc[0][1] += a.x * b.y;
            acc[0][2] += a.x * b.z; acc[0][3] += a.x * b.w;
            acc[1][0] += a.y * b.x; acc[1][1] += a.y * b.y;
            acc[1][2] += a.y * b.z; acc[1][3] += a.y * b.w;
            acc[2][0] += a.z * b.x; acc[2][1] += a.z * b.y;
            acc[2][2] += a.z * b.z; acc[2][3] += a.z * b.w;
            acc[3][0] += a.w * b.x; acc[3][1] += a.w * b.y;
            acc[3][2] += a.w * b.z; acc[3][3] += a.w * b.w;
        }
    }

    float* __restrict__ outp = g_part + s * (NROWS * NROWS);
    const int row0 = bm * TILE + 4 * ty;
    const int col0 = bn * TILE + 4 * tx;
#pragma unroll
    for (int i = 0; i < 4; i++)
        *(float4*)&outp[(row0 + i) * NROWS + col0] =
            make_float4(acc[i][0], acc[i][1], acc[i][2], acc[i][3]);

    if (bm == bn && tx == ty) {
#pragma unroll
        for (int d = 0; d < 4; d++) g_diag[s][row0 + d] = acc[d][d];
    }
}

// ---------------------------------------------------------------------------
// Kernel 2: triplet sum, warp-per-anchor. 64 blocks x 256 threads.
// Balanced mapping: anchor = w*64 + blockIdx.x. Phase A: batched LDGs sum
// the 4 k-split partials per slot (deep MLP). Phase B: uniform ballot
// compaction of positives. Hot loop: np x 16 unrolled register fmax.
// One atomicAdd per block.
// ---------------------------------------------------------------------------
__global__ void triplet_kernel(const void* __restrict__ idxraw,
                               float* __restrict__ out) {
    const int tid  = threadIdx.x;
    const int w    = tid >> 5;
    const int lane = tid & 31;

    __shared__ float s_inv[NROWS];
    __shared__ int   s_cls[NROWS];
    __shared__ float s_pos[8][32];
    __shared__ float s_wsum[8];

    const int is32 = g_idx32;
    const int* __restrict__ i32 = (const int*)idxraw;
    const long long* __restrict__ i64 = (const long long*)idxraw;

#pragma unroll
    for (int e = 0; e < 2; e++) {
        int r = tid + e * 256;
        float d = 0.f;
#pragma unroll
        for (int p = 0; p < KSPLIT; p++) d += g_diag[p][r];   // coalesced
        s_inv[r] = 1.0f / fmaxf(sqrtf(d), 1e-8f);
        s_cls[r] = is32 ? i32[r] : (int)i64[r];
    }
    __syncthreads();

    const int i = w * 64 + blockIdx.x;        // balanced anchor mapping
    const int   ci   = s_cls[i];
    const float invi = s_inv[i];
    const int   rowbase = i * NROWS;

    // Phase A: batched partial-sum loads; no warp collectives here.
    float c[16];
#pragma unroll
    for (int slot = 0; slot < 16; slot++) {
        int j = i + 1 + lane + slot * 32;
        float sum = 0.f;
        if (j < NROWS) {
#pragma unroll
            for (int p = 0; p < KSPLIT; p++)
                sum += g_part[p * (NROWS * NROWS) + rowbase + j];
            sum *= invi * s_inv[j];
        }
        c[slot] = sum;
    }

    // Phase B: uniform ballot compaction (all lanes hit every ballot).
    int np = 0;
#pragma unroll
    for (int slot = 0; slot < 16; slot++) {
        int j = i + 1 + lane + slot * 32;
        bool valid = (j < NROWS);
        bool match = valid && (s_cls[j] == ci);
        unsigned mask = __ballot_sync(0xffffffffu, match);
        if (match) {
            int off = np + __popc(mask & ((1u << lane) - 1u));
            if (off < 32) s_pos[w][off] = c[slot];
        }
        np += __popc(mask);
        c[slot] = (valid && !match) ? (c[slot] + 1.0f) : -1e30f;  // sentinel
    }
    if (np > 32) np = 32;   // capacity guard (expected np ~ 4)
    __syncwarp();

    // Hot loop: np broadcast-LDS reads, 16 unrolled register fmax each.
    float s0 = 0.f, s1 = 0.f;
    for (int p = 0; p < np; p++) {
        float bp = s_pos[w][p];
#pragma unroll
        for (int slot = 0; slot < 16; slot += 2) {
            s0 += fmaxf(c[slot]     - bp, 0.0f);
            s1 += fmaxf(c[slot + 1] - bp, 0.0f);
        }
    }
    float s = s0 + s1;

#pragma unroll
    for (int o = 16; o; o >>= 1) s += __shfl_xor_sync(0xffffffffu, s, o);
    if (lane == 0) s_wsum[w] = s;
    __syncthreads();

    if (tid < 8) {
        float v = s_wsum[tid];
#pragma unroll
        for (int o = 4; o; o >>= 1) v += __shfl_xor_sync(0xffu, v, o);
        if (tid == 0) atomicAdd(out, v);   // one atomic per block (64 total)
    }
}

extern "C" void kernel_launch(void* const* d_in, const int* in_sizes, int n_in,
                              void* d_out, int out_size) {
    const float* embs = (const float*)d_in[0];
    const void*  indices = d_in[1];
    float* out = (float*)d_out;

    gemm_kernel<<<GEMM_GRID, 256>>>(embs, (const int*)indices, out);
    triplet_kernel<<<64, 256>>>(indices, out);
}